// round 1
// baseline (speedup 1.0000x reference)
#include <cuda_runtime.h>
#include <cstdint>

#define NB   256      // bins per batch (fixed by problem)
#define BPB  77       // blocks per batch for the main kernel (157696/4/256/77 = 2 float4/thread)
#define MAXB 8

// persistent scratch (re-initialized every launch by k_sort)
__device__ float    g_sorted[MAXB * NB];
__device__ unsigned g_gapmax[MAXB * (NB + 1)];
__device__ unsigned g_gapmin[MAXB * (NB + 1)];
__device__ float    g_psum[MAXB * BPB];
__device__ float    g_pcnt[MAXB * BPB];

// ---------------------------------------------------------------------------
// Kernel 0: per-batch bitonic sort of the 256 bin centers + scratch init
// ---------------------------------------------------------------------------
__global__ void __launch_bounds__(NB) k_sort(const float* __restrict__ bins)
{
    __shared__ float s[NB];
    int b = blockIdx.x, t = threadIdx.x;
    s[t] = bins[b * NB + t];
    __syncthreads();
    for (int k = 2; k <= NB; k <<= 1) {
        for (int j = k >> 1; j > 0; j >>= 1) {
            int ixj = t ^ j;
            if (ixj > t) {
                float a = s[t], c = s[ixj];
                bool up = ((t & k) == 0);
                if ((a > c) == up) { s[t] = c; s[ixj] = a; }
            }
            __syncthreads();
        }
    }
    g_sorted[b * NB + t] = s[t];
    g_gapmax[b * (NB + 1) + t] = 0u;            // 0.0f == "empty" (valid pts >= 0.001)
    g_gapmin[b * (NB + 1) + t] = 0x7f800000u;   // +inf  == "empty"
    if (t == 0) {
        g_gapmax[b * (NB + 1) + NB] = 0u;
        g_gapmin[b * (NB + 1) + NB] = 0x7f800000u;
    }
}

// ---------------------------------------------------------------------------
// per-point work: binary search nearest bin (dir 1) + gap tally (dir 2)
// ---------------------------------------------------------------------------
__device__ __forceinline__ void process_point(
    float pv, const float* __restrict__ sc,
    unsigned* __restrict__ gmax, unsigned* __restrict__ gmin,
    float& sumA, float& cnt)
{
    // g = number of sorted bins <= pv, in [0, 256]
    int g = 0;
#pragma unroll
    for (int s2 = NB / 2; s2; s2 >>= 1) {
        int nt = g + s2;
        if (sc[nt - 1] <= pv) g = nt;
    }
    float dlo = (g > 0)  ? (pv - sc[g - 1]) : 3e18f;
    float dhi = (g < NB) ? (sc[g] - pv)     : 3e18f;
    float dmin = fminf(dlo * dlo, dhi * dhi);

    if (pv >= 0.001f) {                         // same constant as reference mask
        sumA += dmin;
        cnt  += 1.0f;
        unsigned pb = __float_as_uint(pv);      // pv > 0 -> uint order == float order
        atomicMax(&gmax[g], pb);
        atomicMin(&gmin[g], pb);
    }
}

// ---------------------------------------------------------------------------
// Kernel 1: main pass over depth points. grid = (BPB, B), block = 256
// ---------------------------------------------------------------------------
__global__ void __launch_bounds__(NB) k_main(const float* __restrict__ pts, int V)
{
    __shared__ float sc[NB];
    __shared__ float rs[8], rc[8];
    int b = blockIdx.y, t = threadIdx.x;
    sc[t] = g_sorted[b * NB + t];
    __syncthreads();

    const float* p = pts + (size_t)b * V;
    unsigned* gmax = g_gapmax + b * (NB + 1);
    unsigned* gmin = g_gapmin + b * (NB + 1);

    float sumA = 0.0f, cnt = 0.0f;
    int V4 = V >> 2;
    const float4* p4 = reinterpret_cast<const float4*>(p);
    for (int i = blockIdx.x * blockDim.x + t; i < V4; i += BPB * NB) {
        float4 q = p4[i];
        process_point(q.x, sc, gmax, gmin, sumA, cnt);
        process_point(q.y, sc, gmax, gmin, sumA, cnt);
        process_point(q.z, sc, gmax, gmin, sumA, cnt);
        process_point(q.w, sc, gmax, gmin, sumA, cnt);
    }
    if (blockIdx.x == 0 && t < (V & 3)) {       // tail guard (V%4==0 for this problem)
        process_point(p[(V & ~3) + t], sc, gmax, gmin, sumA, cnt);
    }

    // deterministic block reduction into fixed per-block slots
    int lane = t & 31, w = t >> 5;
#pragma unroll
    for (int o = 16; o; o >>= 1) {
        sumA += __shfl_down_sync(0xffffffffu, sumA, o);
        cnt  += __shfl_down_sync(0xffffffffu, cnt,  o);
    }
    if (lane == 0) { rs[w] = sumA; rc[w] = cnt; }
    __syncthreads();
    if (t == 0) {
        float s = 0.0f, c = 0.0f;
        for (int i = 0; i < 8; i++) { s += rs[i]; c += rc[i]; }
        g_psum[b * BPB + blockIdx.x] = s;
        g_pcnt[b * BPB + blockIdx.x] = c;
    }
}

// ---------------------------------------------------------------------------
// Kernel 2: finalize. One block of 256 threads.
// ---------------------------------------------------------------------------
__global__ void __launch_bounds__(NB) k_fin(float* __restrict__ out, int B)
{
    __shared__ float sh8[8], wtot[8];
    __shared__ float sh_n[MAXB], sh_sA[MAXB];
    __shared__ float s_above[NB];
    int t = threadIdx.x, lane = t & 31, w = t >> 5;

    // per-batch sumA / valid-count from partial slots (fixed reduction order)
    for (int b = 0; b < B; b++) {
        float s = 0.0f, c = 0.0f;
        if (t < BPB) { s = g_psum[b * BPB + t]; c = g_pcnt[b * BPB + t]; }
#pragma unroll
        for (int o = 16; o; o >>= 1) {
            s += __shfl_down_sync(0xffffffffu, s, o);
            c += __shfl_down_sync(0xffffffffu, c, o);
        }
        if (lane == 0) { sh8[w] = s; wtot[w] = c; }
        __syncthreads();
        if (t == 0) {
            float ss = 0.0f, cc = 0.0f;
            for (int i = 0; i < 8; i++) { ss += sh8[i]; cc += wtot[i]; }
            sh_sA[b] = ss; sh_n[b] = cc;
        }
        __syncthreads();
    }

    float Lmax = 0.0f;
    for (int b = 0; b < B; b++) Lmax = fmaxf(Lmax, sh_n[b]);

    float total = 0.0f;  // meaningful in thread 0 only
    for (int b = 0; b < B; b++) {
        float c  = g_sorted[b * NB + t];
        float c2 = c * c;

        // min over bins of c^2 (broadcast)
        float m = c2;
#pragma unroll
        for (int o = 16; o; o >>= 1) m = fminf(m, __shfl_down_sync(0xffffffffu, m, o));
        if (lane == 0) sh8[w] = m;
        __syncthreads();
        float minc2 = sh8[0];
        for (int i = 1; i < 8; i++) minc2 = fminf(minc2, sh8[i]);
        __syncthreads();

        // nearest valid point BELOW bin t: inclusive prefix-max of gap maxes 0..t
        unsigned mb = g_gapmax[b * (NB + 1) + t];
        float below = (mb == 0u) ? -3e18f : __uint_as_float(mb);
#pragma unroll
        for (int o = 1; o < 32; o <<= 1) {
            float u = __shfl_up_sync(0xffffffffu, below, o);
            if (lane >= o) below = fmaxf(below, u);
        }
        if (lane == 31) wtot[w] = below;
        __syncthreads();
        float carry = -3e18f;
        for (int i = 0; i < w; i++) carry = fmaxf(carry, wtot[i]);
        below = fmaxf(below, carry);
        __syncthreads();

        // nearest valid point ABOVE bin j: suffix-min of gap mins j+1..256.
        // thread t loads gap (256 - t); inclusive prefix-min; bin j reads slot 255-j.
        unsigned ma = g_gapmin[b * (NB + 1) + (NB - t)];
        float above = (ma == 0x7f800000u) ? 3e18f : __uint_as_float(ma);
#pragma unroll
        for (int o = 1; o < 32; o <<= 1) {
            float u = __shfl_up_sync(0xffffffffu, above, o);
            if (lane >= o) above = fminf(above, u);
        }
        if (lane == 31) wtot[w] = above;
        __syncthreads();
        float carry2 = 3e18f;
        for (int i = 0; i < w; i++) carry2 = fminf(carry2, wtot[i]);
        above = fminf(above, carry2);
        s_above[t] = above;
        __syncthreads();
        float ab = s_above[NB - 1 - t];

        float d1 = c - below;     // sentinel -> ~9e36 (finite, never the min)
        float d2 = ab - c;
        float mv = fminf(d1 * d1, d2 * d2);
        float npad = Lmax - sh_n[b];
        if (npad > 0.0f) mv = fminf(mv, c2);   // zero pad-point candidate

        // sum over bins
#pragma unroll
        for (int o = 16; o; o >>= 1) mv += __shfl_down_sync(0xffffffffu, mv, o);
        if (lane == 0) sh8[w] = mv;
        __syncthreads();
        if (t == 0) {
            float sB = 0.0f;
            for (int i = 0; i < 8; i++) sB += sh8[i];
            total += sh_sA[b] + npad * minc2 + sB;
        }
        __syncthreads();
    }
    if (t == 0) out[0] = total / (float)B;
}

// ---------------------------------------------------------------------------
extern "C" void kernel_launch(void* const* d_in, const int* in_sizes, int n_in,
                              void* d_out, int out_size)
{
    const float* bins = (const float*)d_in[0];
    const float* pts  = (const float*)d_in[1];
    int sb = in_sizes[0], sp = in_sizes[1];
    if (sb > sp) {                 // defensive: detect swapped input order by size
        const float* tmp = bins; bins = pts; pts = tmp;
        int ts = sb; sb = sp; sp = ts;
    }
    int B = sb / NB;               // 4
    int V = sp / B;                // 157696

    k_sort<<<B, NB>>>(bins);
    dim3 grid1(BPB, B);
    k_main<<<grid1, NB>>>(pts, V);
    k_fin<<<1, NB>>>((float*)d_out, B);
}

// round 2
// speedup vs baseline: 2.4766x; 2.4766x over previous
#include <cuda_runtime.h>

#define NB        256   // bins per batch
#define BPB       74    // blocks per batch: 4*74 = 296 = 2 blocks/SM on 148 SMs
#define MAXB      8
#define NGAP      (NB + 1)
#define GAPSTRIDE 8     // 32B per gap slot -> spread atomics across many L2 lines

// Static zero-init scratch. Final block re-zeros gap arrays + counter each launch.
__device__ unsigned g_gapmax [MAXB * NGAP * GAPSTRIDE];  // max of float bits (pv>0)
__device__ unsigned g_gapminN[MAXB * NGAP * GAPSTRIDE];  // max of ~bits == ~(min bits)
__device__ float    g_sorted[MAXB * NB];
__device__ float    g_psum[MAXB * BPB];
__device__ float    g_pcnt[MAXB * BPB];
__device__ unsigned g_arrive;

__device__ __forceinline__ unsigned vldu(const unsigned* p) {
    return *(const volatile unsigned*)p;
}
__device__ __forceinline__ float vldf(const float* p) {
    return *(const volatile float*)p;
}

// per-point: binary search nearest bin (dir 1) + shared gap tally (dir 2)
__device__ __forceinline__ void process_point(
    float pv, const float* __restrict__ sc,
    unsigned* smax, unsigned* sminN,
    float& sumA, float& cnt)
{
    int g = 0;                                   // #bins <= pv, in [0,256]
#pragma unroll
    for (int s2 = NB / 2; s2; s2 >>= 1) {
        int nt = g + s2;
        if (sc[nt - 1] <= pv) g = nt;
    }
    float dlo = (g > 0)  ? (pv - sc[g - 1]) : 3e18f;
    float dhi = (g < NB) ? (sc[g] - pv)     : 3e18f;

    if (pv >= 0.001f) {                          // same mask constant as reference
        sumA += fminf(dlo * dlo, dhi * dhi);
        cnt  += 1.0f;
        unsigned pb = __float_as_uint(pv);       // pv>0 -> uint order == float order
        if (pb > smax[g])  atomicMax(&smax[g],  pb);   // stale-read skip is safe (monotonic)
        unsigned nbts = ~pb;
        if (nbts > sminN[g]) atomicMax(&sminN[g], nbts);
    }
}

__global__ void __launch_bounds__(NB)
k_all(const float* __restrict__ bins, const float* __restrict__ pts,
      int V, int B, float* __restrict__ out)
{
    __shared__ float    sc[NB];
    __shared__ unsigned smax[NGAP], sminN[NGAP];
    __shared__ float    red[8], red2[8];
    __shared__ float    s_above[NB];
    __shared__ float    sh_n[MAXB], sh_sA[MAXB];
    __shared__ int      s_last;

    const int b = blockIdx.y, t = threadIdx.x;
    const int lane = t & 31, w = t >> 5;

    // ---- load + per-block bitonic sort of this batch's bins ----------------
    sc[t] = bins[b * NB + t];
    smax[t] = 0u; sminN[t] = 0u;
    if (t == 0) { smax[NB] = 0u; sminN[NB] = 0u; }
    __syncthreads();
    for (int k = 2; k <= NB; k <<= 1) {
        for (int j = k >> 1; j > 0; j >>= 1) {
            int ixj = t ^ j;
            if (ixj > t) {
                float a = sc[t], c = sc[ixj];
                bool up = ((t & k) == 0);
                if ((a > c) == up) { sc[t] = c; sc[ixj] = a; }
            }
            __syncthreads();
        }
    }

    // ---- main pass over this block's slice of depth points -----------------
    const float* p = pts + (size_t)b * V;
    float sumA = 0.0f, cnt = 0.0f;
    const int V4 = V >> 2;
    const float4* p4 = reinterpret_cast<const float4*>(p);
    for (int i = blockIdx.x * NB + t; i < V4; i += BPB * NB) {
        float4 q = p4[i];
        process_point(q.x, sc, smax, sminN, sumA, cnt);
        process_point(q.y, sc, smax, sminN, sumA, cnt);
        process_point(q.z, sc, smax, sminN, sumA, cnt);
        process_point(q.w, sc, smax, sminN, sumA, cnt);
    }
    if (blockIdx.x == 0 && t < (V & 3))
        process_point(p[(V & ~3) + t], sc, smax, sminN, sumA, cnt);

    // ---- deterministic block reduction of sumA / cnt -----------------------
#pragma unroll
    for (int o = 16; o; o >>= 1) {
        sumA += __shfl_down_sync(0xffffffffu, sumA, o);
        cnt  += __shfl_down_sync(0xffffffffu, cnt,  o);
    }
    if (lane == 0) { red[w] = sumA; red2[w] = cnt; }
    __syncthreads();
    if (t == 0) {
        float s = 0.0f, c = 0.0f;
        for (int i = 0; i < 8; i++) { s += red[i]; c += red2[i]; }
        g_psum[b * BPB + blockIdx.x] = s;
        g_pcnt[b * BPB + blockIdx.x] = c;
    }

    // ---- flush shared gap tallies to padded global slots --------------------
    __syncthreads();   // all shared atomics done
    for (int i = t; i < NGAP; i += NB) {
        unsigned m = smax[i];
        if (m)  atomicMax(&g_gapmax [(b * NGAP + i) * GAPSTRIDE], m);
        unsigned n2 = sminN[i];
        if (n2) atomicMax(&g_gapminN[(b * NGAP + i) * GAPSTRIDE], n2);
    }
    if (blockIdx.x == 0) g_sorted[b * NB + t] = sc[t];

    // ---- arrival: last block finalizes --------------------------------------
    __threadfence();
    __syncthreads();
    if (t == 0) {
        unsigned total = gridDim.x * gridDim.y;
        unsigned old = atomicAdd(&g_arrive, 1u);
        s_last = (old == total - 1u) ? 1 : 0;
    }
    __syncthreads();
    if (!s_last) return;
    __threadfence();   // acquire side

    // ======================= FINALIZE (one block) ============================
    // per-batch sumA / valid-count from partial slots (fixed reduction order)
    for (int bb = 0; bb < B; bb++) {
        float s = 0.0f, c = 0.0f;
        if (t < BPB) { s = vldf(&g_psum[bb * BPB + t]); c = vldf(&g_pcnt[bb * BPB + t]); }
#pragma unroll
        for (int o = 16; o; o >>= 1) {
            s += __shfl_down_sync(0xffffffffu, s, o);
            c += __shfl_down_sync(0xffffffffu, c, o);
        }
        if (lane == 0) { red[w] = s; red2[w] = c; }
        __syncthreads();
        if (t == 0) {
            float ss = 0.0f, cc = 0.0f;
            for (int i = 0; i < 8; i++) { ss += red[i]; cc += red2[i]; }
            sh_sA[bb] = ss; sh_n[bb] = cc;
        }
        __syncthreads();
    }

    float Lmax = 0.0f;
    for (int bb = 0; bb < B; bb++) Lmax = fmaxf(Lmax, sh_n[bb]);

    float total_loss = 0.0f;   // meaningful in thread 0 only
    for (int bb = 0; bb < B; bb++) {
        float c  = vldf(&g_sorted[bb * NB + t]);
        float c2 = c * c;

        // min over bins of c^2
        float m = c2;
#pragma unroll
        for (int o = 16; o; o >>= 1) m = fminf(m, __shfl_down_sync(0xffffffffu, m, o));
        if (lane == 0) red[w] = m;
        __syncthreads();
        float minc2 = red[0];
        for (int i = 1; i < 8; i++) minc2 = fminf(minc2, red[i]);
        __syncthreads();

        // nearest valid point BELOW bin t: prefix-max of gap maxes 0..t
        unsigned mb = vldu(&g_gapmax[(bb * NGAP + t) * GAPSTRIDE]);
        float below = (mb == 0u) ? -3e18f : __uint_as_float(mb);
#pragma unroll
        for (int o = 1; o < 32; o <<= 1) {
            float u = __shfl_up_sync(0xffffffffu, below, o);
            if (lane >= o) below = fmaxf(below, u);
        }
        if (lane == 31) red2[w] = below;
        __syncthreads();
        float carry = -3e18f;
        for (int i = 0; i < w; i++) carry = fmaxf(carry, red2[i]);
        below = fmaxf(below, carry);
        __syncthreads();

        // nearest valid point ABOVE bin j: suffix-min of gap mins j+1..256.
        // thread t loads gap (256 - t); prefix-min; bin j reads slot 255-j.
        unsigned na = vldu(&g_gapminN[(bb * NGAP + (NB - t)) * GAPSTRIDE]);
        float above = (na == 0u) ? 3e18f : __uint_as_float(~na);
#pragma unroll
        for (int o = 1; o < 32; o <<= 1) {
            float u = __shfl_up_sync(0xffffffffu, above, o);
            if (lane >= o) above = fminf(above, u);
        }
        if (lane == 31) red2[w] = above;
        __syncthreads();
        float carry2 = 3e18f;
        for (int i = 0; i < w; i++) carry2 = fminf(carry2, red2[i]);
        above = fminf(above, carry2);
        s_above[t] = above;
        __syncthreads();
        float ab = s_above[NB - 1 - t];

        float d1 = c - below;        // sentinels -> ~9e36, never the min
        float d2 = ab - c;
        float mv = fminf(d1 * d1, d2 * d2);
        float npad = Lmax - sh_n[bb];
        if (npad > 0.0f) mv = fminf(mv, c2);   // zero pad-point candidate

#pragma unroll
        for (int o = 16; o; o >>= 1) mv += __shfl_down_sync(0xffffffffu, mv, o);
        if (lane == 0) red[w] = mv;
        __syncthreads();
        if (t == 0) {
            float sB = 0.0f;
            for (int i = 0; i < 8; i++) sB += red[i];
            total_loss += sh_sA[bb] + npad * minc2 + sB;
        }
        __syncthreads();
    }
    if (t == 0) out[0] = total_loss / (float)B;

    // ---- reset scratch for next graph replay --------------------------------
    __syncthreads();   // all reads above complete
    for (int i = t; i < MAXB * NGAP; i += NB) {
        g_gapmax [i * GAPSTRIDE] = 0u;
        g_gapminN[i * GAPSTRIDE] = 0u;
    }
    if (t == 0) g_arrive = 0u;
}

// ---------------------------------------------------------------------------
extern "C" void kernel_launch(void* const* d_in, const int* in_sizes, int n_in,
                              void* d_out, int out_size)
{
    const float* bins = (const float*)d_in[0];
    const float* pts  = (const float*)d_in[1];
    int sb = in_sizes[0], sp = in_sizes[1];
    if (sb > sp) {                 // defensive: detect swapped input order
        const float* tmp = bins; bins = pts; pts = tmp;
        int ts = sb; sb = sp; sp = ts;
    }
    int B = sb / NB;               // 4
    int V = sp / B;                // 157696

    dim3 grid(BPB, B);
    k_all<<<grid, NB>>>(bins, pts, V, B, (float*)d_out);
}